// round 13
// baseline (speedup 1.0000x reference)
#include <cuda_runtime.h>
#include <cuda_bf16.h>
#include <math.h>
#include <stdint.h>

#define Bb 2
#define LL 2048
#define DD 2048
#define HH 16
#define DHd 128
#define MM (Bb*LL)   // 4096
#define SLW (DD*DD)

// Scratch (allocation-free), all bf16 hi/lo pairs
__device__ __nv_bfloat16 g_ah[MM * DD];
__device__ __nv_bfloat16 g_al[MM * DD];
__device__ __nv_bfloat16 g_wh[4 * SLW];
__device__ __nv_bfloat16 g_wl[4 * SLW];
__device__ __nv_bfloat16 g_qh[MM * DD];
__device__ __nv_bfloat16 g_ql[MM * DD];
__device__ __nv_bfloat16 g_kh[MM * DD];
__device__ __nv_bfloat16 g_kl[MM * DD];
__device__ __nv_bfloat16 g_vh[MM * DD];
__device__ __nv_bfloat16 g_vl[MM * DD];
__device__ __nv_bfloat16 g_oh[MM * DD];
__device__ __nv_bfloat16 g_ol[MM * DD];

// ---------------------------------------------------------------------------
// PTX helpers (non-'a' target: mma.sync / ldmatrix / cp.async)
// ---------------------------------------------------------------------------
__device__ __forceinline__ uint32_t s2u(const void* p) {
    uint32_t a;
    asm("{ .reg .u64 t; cvta.to.shared.u64 t, %1; cvt.u32.u64 %0, t; }"
        : "=r"(a) : "l"(p));
    return a;
}
__device__ __forceinline__ void cp16(uint32_t so, const void* g) {
    asm volatile("cp.async.cg.shared.global [%0], [%1], 16;" :: "r"(so), "l"(g));
}
#define CP_COMMIT() asm volatile("cp.async.commit_group;" ::: "memory")
#define CP_WAIT(n)  asm volatile("cp.async.wait_group %0;" :: "n"(n) : "memory")

__device__ __forceinline__ void ldsm4(uint32_t* d, uint32_t a) {
    asm volatile("ldmatrix.sync.aligned.m8n8.x4.shared.b16 {%0,%1,%2,%3}, [%4];"
                 : "=r"(d[0]), "=r"(d[1]), "=r"(d[2]), "=r"(d[3]) : "r"(a));
}
__device__ __forceinline__ void ldsm4t(uint32_t* d, uint32_t a) {
    asm volatile("ldmatrix.sync.aligned.m8n8.x4.trans.shared.b16 {%0,%1,%2,%3}, [%4];"
                 : "=r"(d[0]), "=r"(d[1]), "=r"(d[2]), "=r"(d[3]) : "r"(a));
}
__device__ __forceinline__ void mma16816(float* c, const uint32_t* a,
                                         uint32_t b0, uint32_t b1) {
    asm volatile(
        "mma.sync.aligned.m16n8k16.row.col.f32.bf16.bf16.f32 "
        "{%0,%1,%2,%3}, {%4,%5,%6,%7}, {%8,%9}, {%0,%1,%2,%3};"
        : "+f"(c[0]), "+f"(c[1]), "+f"(c[2]), "+f"(c[3])
        : "r"(a[0]), "r"(a[1]), "r"(a[2]), "r"(a[3]), "r"(b0), "r"(b1));
}
__device__ __forceinline__ void split2(float f0, float f1,
                                       __nv_bfloat162& h, __nv_bfloat162& l) {
    h = __floats2bfloat162_rn(f0, f1);
    float2 hf = __bfloat1622float2(h);
    l = __floats2bfloat162_rn(f0 - hf.x, f1 - hf.y);
}

// ---------------------------------------------------------------------------
// Splits: fp32 -> bf16 hi/lo.  x separately; 4 weights merged (grid.y = 4).
// ---------------------------------------------------------------------------
__global__ void __launch_bounds__(256) split_bf16(
    const float* __restrict__ s, __nv_bfloat16* __restrict__ h,
    __nv_bfloat16* __restrict__ l)
{
    const int i = blockIdx.x * 256 + threadIdx.x;
    float4 f = ((const float4*)s)[i];
    __nv_bfloat162 h0, h1, l0, l1;
    split2(f.x, f.y, h0, l0);
    split2(f.z, f.w, h1, l1);
    ((__nv_bfloat162*)h)[2*i]   = h0;
    ((__nv_bfloat162*)h)[2*i+1] = h1;
    ((__nv_bfloat162*)l)[2*i]   = l0;
    ((__nv_bfloat162*)l)[2*i+1] = l1;
}

__global__ void __launch_bounds__(256) split_w4(
    const float* __restrict__ w0, const float* __restrict__ w1,
    const float* __restrict__ w2, const float* __restrict__ w3,
    __nv_bfloat16* __restrict__ h, __nv_bfloat16* __restrict__ l)
{
    const int z = blockIdx.y;
    const float* s = (z == 0) ? w0 : (z == 1) ? w1 : (z == 2) ? w2 : w3;
    const int i = blockIdx.x * 256 + threadIdx.x;
    float4 f = ((const float4*)s)[i];
    __nv_bfloat162 h0, h1, l0, l1;
    split2(f.x, f.y, h0, l0);
    split2(f.z, f.w, h1, l1);
    const size_t o = (size_t)z * (SLW / 2) + 2 * i;
    ((__nv_bfloat162*)h)[o]     = h0;
    ((__nv_bfloat162*)h)[o + 1] = h1;
    ((__nv_bfloat162*)l)[o]     = l0;
    ((__nv_bfloat162*)l)[o + 1] = l1;
}

// ---------------------------------------------------------------------------
// GEMM: C = A*W^T, bf16 hi/lo 3-product, fp32 accum.  (unchanged from R11)
// BM=128 BN=64 BK=32. 256 thr, 2 CTAs/SM, 3-stage cp.async pipeline.
// ---------------------------------------------------------------------------
#define ROWB 80
#define AT64 (128 * ROWB)           // 10240
#define BT64 (64 * ROWB)            // 5120
#define STG64 (2 * AT64 + 2 * BT64) // 30720
#define GSMEM (3 * STG64)           // 92160

__device__ __forceinline__ void load_stage64(
    uint32_t sb, int stage, int tid, int m0, int n0, int kt,
    const __nv_bfloat16* __restrict__ Ah, const __nv_bfloat16* __restrict__ Al,
    const __nv_bfloat16* __restrict__ Bh, const __nv_bfloat16* __restrict__ Bl)
{
    const uint32_t base = sb + stage * STG64;
    const int k0 = kt * 32;
#pragma unroll
    for (int j = 0; j < 2; j++) {
        const int idx = tid + j * 256;
        const int r = idx >> 2, c16 = idx & 3;
        const uint32_t so = r * ROWB + c16 * 16;
        const size_t ga = (size_t)(m0 + r) * DD + k0 + c16 * 8;
        cp16(base + so,        Ah + ga);
        cp16(base + AT64 + so, Al + ga);
    }
    {
        const int r = tid >> 2, c16 = tid & 3;
        const uint32_t so = r * ROWB + c16 * 16;
        const size_t gw = (size_t)(n0 + r) * DD + k0 + c16 * 8;
        cp16(base + 2 * AT64 + so,        Bh + gw);
        cp16(base + 2 * AT64 + BT64 + so, Bl + gw);
    }
}

__global__ void __launch_bounds__(256, 2) gemm64(
    const __nv_bfloat16* __restrict__ Ah, const __nv_bfloat16* __restrict__ Al,
    const __nv_bfloat16* __restrict__ Wh, const __nv_bfloat16* __restrict__ Wl,
    float* __restrict__ Cf,
    __nv_bfloat16* __restrict__ qh, __nv_bfloat16* __restrict__ ql,
    __nv_bfloat16* __restrict__ kh, __nv_bfloat16* __restrict__ kl,
    __nv_bfloat16* __restrict__ vh, __nv_bfloat16* __restrict__ vl,
    const float* __restrict__ cosb, const float* __restrict__ sinb, int qkv)
{
    extern __shared__ char sm[];
    const uint32_t sb = s2u(sm);
    const int tid = threadIdx.x, wid = tid >> 5, lid = tid & 31;
    const int lr = lid & 15, lh = lid >> 4;
    const int m0 = blockIdx.y * 128, n0 = blockIdx.x * 64;
    const int z = blockIdx.z;
    const int m0w = (wid & 3) * 32;
    const int n0w = (wid >> 2) * 32;

    const __nv_bfloat16* Bh = Wh + (size_t)(qkv ? z : 0) * SLW;
    const __nv_bfloat16* Bl = Wl + (size_t)(qkv ? z : 0) * SLW;
    const int mode = qkv ? ((z == 0) ? 2 : (z == 1) ? 1 : 3) : 0;
    __nv_bfloat16 *Ch = nullptr, *Cl = nullptr;
    if (qkv) {
        if (z == 0)      { Ch = qh; Cl = ql; }
        else if (z == 1) { Ch = kh; Cl = kl; }
        else             { Ch = vh; Cl = vl; }
    }

    float acc[2][4][4];
#pragma unroll
    for (int a = 0; a < 2; a++)
#pragma unroll
        for (int b = 0; b < 4; b++)
#pragma unroll
            for (int c = 0; c < 4; c++) acc[a][b][c] = 0.f;

    load_stage64(sb, 0, tid, m0, n0, 0, Ah, Al, Bh, Bl);
    CP_COMMIT();
    load_stage64(sb, 1, tid, m0, n0, 1, Ah, Al, Bh, Bl);
    CP_COMMIT();

    for (int kt = 0; kt < 64; kt++) {
        if (kt + 1 < 64) { CP_WAIT(1); } else { CP_WAIT(0); }
        __syncthreads();
        if (kt + 2 < 64) {
            load_stage64(sb, (kt + 2) % 3, tid, m0, n0, kt + 2, Ah, Al, Bh, Bl);
            CP_COMMIT();
        }
        const uint32_t bA  = sb + (kt % 3) * STG64;
        const uint32_t bAl = bA + AT64;
        const uint32_t bWh = bA + 2 * AT64;
        const uint32_t bWl = bWh + BT64;

#pragma unroll
        for (int kk = 0; kk < 2; kk++) {
            const int c16 = kk * 2 + lh;
            uint32_t ahf[2][4], alf[2][4];
#pragma unroll
            for (int mt = 0; mt < 2; mt++) {
                const uint32_t off = (m0w + mt * 16 + lr) * ROWB + c16 * 16;
                ldsm4(ahf[mt], bA + off);
                ldsm4(alf[mt], bAl + off);
            }
#pragma unroll
            for (int g = 0; g < 2; g++) {
                const uint32_t offb = (n0w + g * 16 + lr) * ROWB + c16 * 16;
                uint32_t bhf[4], blf[4];
                ldsm4(bhf, bWh + offb);
                ldsm4(blf, bWl + offb);
#pragma unroll
                for (int mt = 0; mt < 2; mt++) {
#pragma unroll
                    for (int nt = 0; nt < 2; nt++) {
                        float* cc = acc[mt][g * 2 + nt];
                        mma16816(cc, ahf[mt], bhf[nt], bhf[nt + 2]);
                        mma16816(cc, ahf[mt], blf[nt], blf[nt + 2]);
                        mma16816(cc, alf[mt], bhf[nt], bhf[nt + 2]);
                    }
                }
            }
        }
    }

    const int gid = lid >> 2, tig = lid & 3;
#pragma unroll
    for (int mt = 0; mt < 2; mt++) {
#pragma unroll
        for (int ix = 0; ix < 4; ix++) {
            const float* cc = acc[mt][ix];
            const int gn = n0 + n0w + ix * 8 + tig * 2;
#pragma unroll
            for (int hrow = 0; hrow < 2; hrow++) {
                const int m = m0 + m0w + mt * 16 + gid + hrow * 8;
                float v0 = cc[hrow * 2], v1 = cc[hrow * 2 + 1];
                if (mode == 1 || mode == 2) {
                    const int lrow = m & (LL - 1);
                    const int ip = (gn & (DHd - 1)) >> 1;
                    const float co = cosb[lrow * 64 + ip];
                    const float si = sinb[lrow * 64 + ip];
                    const float t0 = v0 * co - v1 * si;
                    const float t1 = v0 * si + v1 * co;
                    v0 = t0; v1 = t1;
                    if (mode == 2) { v0 *= 0.08838834764831845f; v1 *= 0.08838834764831845f; }
                }
                const size_t gidx = (size_t)m * DD + gn;
                if (mode == 0) {
                    *(float2*)(Cf + gidx) = make_float2(v0, v1);
                } else {
                    __nv_bfloat162 hb, lb;
                    split2(v0, v1, hb, lb);
                    *(__nv_bfloat162*)(Ch + gidx) = hb;
                    *(__nv_bfloat162*)(Cl + gidx) = lb;
                }
            }
        }
    }
}

// ---------------------------------------------------------------------------
// Flash attention, mma.sync, hi/lo 3-product. R12: 2 CTAs/SM.
// CTA: 64 q rows, 4 warps x 16 rows, 128 threads. 64-key tiles,
// SINGLE-buffered KV (cross-CTA overlap replaces double buffering).
// smem: Qh/Ql 2*17408 + KV 69632 = 104448 -> 2 CTAs/SM.
// ---------------------------------------------------------------------------
#define APITCH 272
#define AQB (64 * APITCH)            // 17408 per Q buffer
#define AKV (4 * 64 * APITCH)        // 69632 KV stage
#define ASMEM (2 * AQB + AKV)        // 104448

__device__ __forceinline__ void load_kv1(
    uint32_t sb, int tid, int b, int k0, int h,
    const __nv_bfloat16* __restrict__ Kh, const __nv_bfloat16* __restrict__ Kl,
    const __nv_bfloat16* __restrict__ Vh, const __nv_bfloat16* __restrict__ Vl)
{
    const uint32_t base = sb + 2 * AQB;
#pragma unroll
    for (int j = 0; j < 8; j++) {
        const int i = tid + j * 128;
        const int r = i >> 4, c = i & 15;
        const uint32_t off = r * APITCH + c * 16;
        const size_t g = (size_t)(b * LL + k0 + r) * DD + h * DHd + c * 8;
        cp16(base + off,         Kh + g);
        cp16(base + 17408 + off, Kl + g);
        cp16(base + 34816 + off, Vh + g);
        cp16(base + 52224 + off, Vl + g);
    }
}

__global__ void __launch_bounds__(128, 2) attn_mma(
    const __nv_bfloat16* __restrict__ Qh, const __nv_bfloat16* __restrict__ Ql,
    const __nv_bfloat16* __restrict__ Kh, const __nv_bfloat16* __restrict__ Kl,
    const __nv_bfloat16* __restrict__ Vh, const __nv_bfloat16* __restrict__ Vl,
    __nv_bfloat16* __restrict__ Oh, __nv_bfloat16* __restrict__ Ol)
{
    extern __shared__ char sm[];
    const uint32_t sb = s2u(sm);
    const int tid = threadIdx.x, wid = tid >> 5, lid = tid & 31;
    const int lr = lid & 15, lh = lid >> 4;
    const int gid = lid >> 2, tig = lid & 3;
    const int qt = (int)gridDim.x - 1 - (int)blockIdx.x;   // heavy first
    const int bh = blockIdx.y;
    const int b = bh >> 4, h = bh & 15;
    const int q0 = qt * 64;

    // Q tiles (hi/lo) via cp.async  (group 0)
#pragma unroll
    for (int j = 0; j < 8; j++) {
        const int i = tid + j * 128;
        const int r = i >> 4, c = i & 15;
        const size_t g = (size_t)(b * LL + q0 + r) * DD + h * DHd + c * 8;
        const uint32_t off = r * APITCH + c * 16;
        cp16(sb + off, Qh + g);
        cp16(sb + AQB + off, Ql + g);
    }
    CP_COMMIT();
    load_kv1(sb, tid, b, 0, h, Kh, Kl, Vh, Vl);   // group 1 (tile 0)
    CP_COMMIT();

    CP_WAIT(1);          // Q ready
    __syncthreads();

    // Q fragments held in registers for the whole kernel
    uint32_t qfh[8][4], qfl[8][4];
    const int wrow = wid * 16;
#pragma unroll
    for (int kc = 0; kc < 8; kc++) {
        const uint32_t off = (wrow + lr) * APITCH + (kc * 2 + lh) * 16;
        ldsm4(qfh[kc], sb + off);
        ldsm4(qfl[kc], sb + AQB + off);
    }

    float oacc[16][4];
#pragma unroll
    for (int i = 0; i < 16; i++)
#pragma unroll
        for (int j = 0; j < 4; j++) oacc[i][j] = 0.f;
    float m_[2] = {-INFINITY, -INFINITY}, l_[2] = {0.f, 0.f};

    const int nt = qt + 1;
    for (int t = 0; t < nt; t++) {
        CP_WAIT(0);
        __syncthreads();     // KV tile t visible to all warps

        const int k0 = t * 64;
        const uint32_t kb  = sb + 2 * AQB;
        const uint32_t klb = kb + 17408;
        const uint32_t vhb = kb + 34816;
        const uint32_t vlb = kb + 52224;

        const int rowmax = q0 + wrow + 15;
        if (k0 <= rowmax) {       // warp-level causal skip
            float sf[8][4];
#pragma unroll
            for (int i = 0; i < 8; i++)
#pragma unroll
                for (int j = 0; j < 4; j++) sf[i][j] = 0.f;

#pragma unroll
            for (int kc = 0; kc < 8; kc++) {
#pragma unroll
                for (int g = 0; g < 4; g++) {
                    const uint32_t off = (g * 16 + lr) * APITCH + (kc * 2 + lh) * 16;
                    uint32_t bhf[4], blf[4];
                    ldsm4(bhf, kb + off);
                    ldsm4(blf, klb + off);
#pragma unroll
                    for (int n2 = 0; n2 < 2; n2++) {
                        float* cc = sf[g * 2 + n2];
                        mma16816(cc, qfh[kc], bhf[n2], bhf[n2 + 2]);
                        mma16816(cc, qfh[kc], blf[n2], blf[n2 + 2]);
                        mma16816(cc, qfl[kc], bhf[n2], bhf[n2 + 2]);
                    }
                }
            }

            if (k0 + 63 > q0 + wrow) {
#pragma unroll
                for (int g8 = 0; g8 < 8; g8++)
#pragma unroll
                    for (int c = 0; c < 4; c++) {
                        const int key = k0 + g8 * 8 + tig * 2 + (c & 1);
                        const int row = q0 + wrow + gid + ((c >> 1) * 8);
                        if (key > row) sf[g8][c] = -1e30f;
                    }
            }

#pragma unroll
            for (int r = 0; r < 2; r++) {
                float tm = -1e30f;
#pragma unroll
                for (int g8 = 0; g8 < 8; g8++)
                    tm = fmaxf(tm, fmaxf(sf[g8][r * 2], sf[g8][r * 2 + 1]));
                tm = fmaxf(tm, __shfl_xor_sync(0xffffffffu, tm, 1));
                tm = fmaxf(tm, __shfl_xor_sync(0xffffffffu, tm, 2));
                const float nm = fmaxf(m_[r], tm);
                const float fac = __expf(m_[r] - nm);
                m_[r] = nm;
                float rs = 0.f;
#pragma unroll
                for (int g8 = 0; g8 < 8; g8++) {
                    const float p0 = __expf(sf[g8][r * 2] - nm);
                    const float p1 = __expf(sf[g8][r * 2 + 1] - nm);
                    sf[g8][r * 2] = p0; sf[g8][r * 2 + 1] = p1;
                    rs += p0 + p1;
                }
                rs += __shfl_xor_sync(0xffffffffu, rs, 1);
                rs += __shfl_xor_sync(0xffffffffu, rs, 2);
                l_[r] = l_[r] * fac + rs;
#pragma unroll
                for (int n16 = 0; n16 < 16; n16++) {
                    oacc[n16][r * 2] *= fac;
                    oacc[n16][r * 2 + 1] *= fac;
                }
            }

#pragma unroll
            for (int kc2 = 0; kc2 < 4; kc2++) {
                uint32_t ph[4], pl[4];
#pragma unroll
                for (int q = 0; q < 4; q++) {
                    const float a = sf[2 * kc2 + (q >> 1)][(q & 1) * 2];
                    const float bfv = sf[2 * kc2 + (q >> 1)][(q & 1) * 2 + 1];
                    __nv_bfloat162 hb, lb;
                    split2(a, bfv, hb, lb);
                    ph[q] = *(uint32_t*)&hb;
                    pl[q] = *(uint32_t*)&lb;
                }
#pragma unroll
                for (int vt = 0; vt < 8; vt++) {
                    const uint32_t off = (kc2 * 16 + lr) * APITCH + (vt * 16 + lh * 8) * 2;
                    uint32_t vhf[4], vlf[4];
                    ldsm4t(vhf, vhb + off);
                    ldsm4t(vlf, vlb + off);
                    float* c0 = oacc[vt * 2];
                    float* c1 = oacc[vt * 2 + 1];
                    mma16816(c0, ph, vhf[0], vhf[1]);
                    mma16816(c1, ph, vhf[2], vhf[3]);
                    mma16816(c0, pl, vhf[0], vhf[1]);
                    mma16816(c1, pl, vhf[2], vhf[3]);
                    mma16816(c0, ph, vlf[0], vlf[1]);
                    mma16816(c1, ph, vlf[2], vlf[3]);
                }
            }
        }

        __syncthreads();     // all warps done reading tile t
        if (t + 1 < nt) {
            load_kv1(sb, tid, b, (t + 1) * 64, h, Kh, Kl, Vh, Vl);
            CP_COMMIT();
        }
    }

    const float inv0 = 1.f / l_[0];
    const float inv1 = 1.f / l_[1];
#pragma unroll
    for (int n16 = 0; n16 < 16; n16++) {
#pragma unroll
        for (int r = 0; r < 2; r++) {
            const float inv = r ? inv1 : inv0;
            const int row = q0 + wrow + gid + r * 8;
            const int col = n16 * 8 + tig * 2;
            const float f0 = oacc[n16][r * 2] * inv;
            const float f1 = oacc[n16][r * 2 + 1] * inv;
            __nv_bfloat162 hb, lb;
            split2(f0, f1, hb, lb);
            const size_t g = (size_t)(b * LL + row) * DD + h * DHd + col;
            *(__nv_bfloat162*)(Oh + g) = hb;
            *(__nv_bfloat162*)(Ol + g) = lb;
        }
    }
}

// ---------------------------------------------------------------------------
extern "C" void kernel_launch(void* const* d_in, const int* in_sizes, int n_in,
                              void* d_out, int out_size)
{
    const float* x    = (const float*)d_in[0];
    const float* cosb = (const float*)d_in[2];
    const float* sinb = (const float*)d_in[3];
    const float* wq   = (const float*)d_in[4];
    const float* wk   = (const float*)d_in[5];
    const float* wv   = (const float*)d_in[6];
    const float* wo   = (const float*)d_in[7];
    float* out = (float*)d_out;

    __nv_bfloat16 *ah, *al, *wh, *wl, *qh, *ql, *kh, *kl, *vh, *vl, *oh, *ol;
    cudaGetSymbolAddress((void**)&ah, g_ah);
    cudaGetSymbolAddress((void**)&al, g_al);
    cudaGetSymbolAddress((void**)&wh, g_wh);
    cudaGetSymbolAddress((void**)&wl, g_wl);
    cudaGetSymbolAddress((void**)&qh, g_qh);
    cudaGetSymbolAddress((void**)&ql, g_ql);
    cudaGetSymbolAddress((void**)&kh, g_kh);
    cudaGetSymbolAddress((void**)&kl, g_kl);
    cudaGetSymbolAddress((void**)&vh, g_vh);
    cudaGetSymbolAddress((void**)&vl, g_vl);
    cudaGetSymbolAddress((void**)&oh, g_oh);
    cudaGetSymbolAddress((void**)&ol, g_ol);

    const int n4x = MM * DD / 4;
    const int n4w = SLW / 4;

    split_bf16<<<n4x / 256, 256>>>(x, ah, al);
    split_w4<<<dim3(n4w / 256, 4), 256>>>(wq, wk, wv, wo, wh, wl);

    cudaFuncSetAttribute(gemm64, cudaFuncAttributeMaxDynamicSharedMemorySize, GSMEM);
    cudaFuncSetAttribute(attn_mma, cudaFuncAttributeMaxDynamicSharedMemorySize, ASMEM);

    // QKV: one merged launch (z = 0,1,2)
    dim3 gqkv(DD / 64, MM / 128, 3);   // 32 x 32 x 3 = 3072 CTAs
    gemm64<<<gqkv, 256, GSMEM>>>(ah, al, wh, wl, nullptr,
                                 qh, ql, kh, kl, vh, vl, cosb, sinb, 1);

    attn_mma<<<dim3(LL / 64, Bb * HH), 128, ASMEM>>>(qh, ql, kh, kl, vh, vl, oh, ol);

    // O projection (fp32 out)
    dim3 go(DD / 64, MM / 128, 1);     // 1024 CTAs
    gemm64<<<go, 256, GSMEM>>>(oh, ol, wh + 3 * (size_t)SLW, wl + 3 * (size_t)SLW,
                               out, nullptr, nullptr, nullptr, nullptr, nullptr, nullptr,
                               cosb, sinb, 0);
}